// round 2
// baseline (speedup 1.0000x reference)
#include <cuda_runtime.h>
#include <cuda_bf16.h>

// Problem dims
#define B_ 2
#define M_ 384
#define N_ 96
#define D_ 512
#define J_ 640
#define C_ 1024
#define MN_ (M_*N_)        // 36864
#define RTOT_ (B_*MN_)     // 73728 rows of the join GEMM

// Scratch for projection outputs (allowed: __device__ globals)
__device__ float g_a[B_*M_*J_];   // [B,M,J] audio projection + bias
__device__ float g_t[B_*N_*J_];   // [B,N,J] text projection + bias

// ---------------------------------------------------------------------------
// helpers
// ---------------------------------------------------------------------------
__device__ __forceinline__ unsigned f2tf32(float x) {
    unsigned r;
    asm("cvt.rna.tf32.f32 %0, %1;" : "=r"(r) : "f"(x));
    return r;
}
__device__ __forceinline__ float fast_tanh(float x) {
    float r;
    asm("tanh.approx.f32 %0, %1;" : "=f"(r) : "f"(x));
    return r;
}
__device__ __forceinline__ void mma_tf32(float d[4],
                                         unsigned a0, unsigned a1, unsigned a2, unsigned a3,
                                         unsigned b0, unsigned b1) {
    asm volatile(
        "mma.sync.aligned.m16n8k8.row.col.f32.tf32.tf32.f32 "
        "{%0,%1,%2,%3}, {%4,%5,%6,%7}, {%8,%9}, {%0,%1,%2,%3};"
        : "+f"(d[0]), "+f"(d[1]), "+f"(d[2]), "+f"(d[3])
        : "r"(a0), "r"(a1), "r"(a2), "r"(a3), "r"(b0), "r"(b1));
}

// ---------------------------------------------------------------------------
// Kernel 1: projection  out[rows,J] = x[rows,D] @ w[D,J] + bias
// which==0 -> g_a, which==1 -> g_t
// blockDim = 320 threads, 8 rows per block, each thread owns 2 adjacent cols
// ---------------------------------------------------------------------------
__global__ __launch_bounds__(320) void proj_kernel(
    const float* __restrict__ x, const float* __restrict__ w,
    const float* __restrict__ bias, int which)
{
    __shared__ float xs[8][D_];
    float* outp = which ? g_t : g_a;

    const int r0  = blockIdx.x * 8;
    const int tid = threadIdx.x;

    for (int i = tid; i < 8 * D_; i += 320) {
        int r = i >> 9;          // /512
        int k = i & (D_ - 1);    // %512
        xs[r][k] = x[(r0 + r) * D_ + k];
    }
    __syncthreads();

    const int j0 = 2 * tid;   // 0..638
    float acc[8][2];
#pragma unroll
    for (int r = 0; r < 8; ++r) { acc[r][0] = 0.f; acc[r][1] = 0.f; }

#pragma unroll 4
    for (int k = 0; k < D_; ++k) {
        float2 wv = *(const float2*)&w[k * J_ + j0];
#pragma unroll
        for (int r = 0; r < 8; ++r) {
            float xv = xs[r][k];
            acc[r][0] += xv * wv.x;
            acc[r][1] += xv * wv.y;
        }
    }

    float2 bb = *(const float2*)&bias[j0];
#pragma unroll
    for (int r = 0; r < 8; ++r) {
        float2 v = make_float2(acc[r][0] + bb.x, acc[r][1] + bb.y);
        *(float2*)&outp[(r0 + r) * J_ + j0] = v;
    }
}

// ---------------------------------------------------------------------------
// Kernel 2: fused join. For row gr = ((b*M+m)*N + n):
//   h[gr,:] = tanh(g_a[b,m,:] + g_t[b,n,:])      (built per K-tile in SMEM, tf32)
//   out[gr,:] = h[gr,:] @ w_join + b_join        (tf32 mma.sync m16n8k8)
// Tile: BM=128 rows x BN=128 cols x BK=32, 256 threads (8 warps: 4x2).
// ---------------------------------------------------------------------------
#define BM 128
#define BN 128
#define BK 32

__global__ __launch_bounds__(256, 2) void join_kernel(
    const float* __restrict__ wj, const float* __restrict__ bj,
    float* __restrict__ out)
{
    __shared__ unsigned hs[BM][BK + 1];   // tf32 bit patterns, padded
    __shared__ unsigned ws[BK][BN + 4];   // tf32 bit patterns, padded
    __shared__ int aoff[BM];
    __shared__ int toff[BM];

    const int tid  = threadIdx.x;
    const int row0 = blockIdx.y * BM;
    const int col0 = blockIdx.x * BN;

    if (tid < BM) {
        int gr  = row0 + tid;
        int b   = gr / MN_;
        int rem = gr - b * MN_;
        int m   = rem / N_;
        int n   = rem - m * N_;
        aoff[tid] = (b * M_ + m) * J_;
        toff[tid] = (b * N_ + n) * J_;
    }
    __syncthreads();

    const int warp = tid >> 5;
    const int lane = tid & 31;
    const int wm   = warp & 3;   // row sub-tile: 32 rows each
    const int wn   = warp >> 2;  // col sub-tile: 64 cols each
    const int g    = lane >> 2;  // groupID
    const int c    = lane & 3;   // threadID in group

    float acc[2][8][4];
#pragma unroll
    for (int mi = 0; mi < 2; ++mi)
#pragma unroll
        for (int ni = 0; ni < 8; ++ni)
#pragma unroll
            for (int q = 0; q < 4; ++q) acc[mi][ni][q] = 0.f;

    // fill-thread mapping
    const int hr = tid >> 3;            // 0..31
    const int hk = (tid & 7) * 4;       // 0,4,...,28
    const int wk = tid >> 5;            // 0..7
    const int wc = (tid & 31) * 4;      // 0..124

    for (int k0 = 0; k0 < J_; k0 += BK) {
        __syncthreads();   // previous tile fully consumed

        // ---- build h tile: tanh(a+t), converted to tf32 ----
#pragma unroll
        for (int rr = 0; rr < 4; ++rr) {
            int row = hr + rr * 32;
            float4 av = *(const float4*)&g_a[aoff[row] + k0 + hk];
            float4 tv = *(const float4*)&g_t[toff[row] + k0 + hk];
            hs[row][hk + 0] = f2tf32(fast_tanh(av.x + tv.x));
            hs[row][hk + 1] = f2tf32(fast_tanh(av.y + tv.y));
            hs[row][hk + 2] = f2tf32(fast_tanh(av.z + tv.z));
            hs[row][hk + 3] = f2tf32(fast_tanh(av.w + tv.w));
        }
        // ---- load w_join tile, convert to tf32 ----
#pragma unroll
        for (int kk = 0; kk < 4; ++kk) {
            int krow = wk + kk * 8;
            float4 wv = *(const float4*)&wj[(k0 + krow) * C_ + col0 + wc];
            ws[krow][wc + 0] = f2tf32(wv.x);
            ws[krow][wc + 1] = f2tf32(wv.y);
            ws[krow][wc + 2] = f2tf32(wv.z);
            ws[krow][wc + 3] = f2tf32(wv.w);
        }
        __syncthreads();

        // ---- compute: 4 k-steps of 8 ----
#pragma unroll
        for (int ks = 0; ks < BK / 8; ++ks) {
            unsigned a_frag[2][4];
#pragma unroll
            for (int mi = 0; mi < 2; ++mi) {
                int rbase = wm * 32 + mi * 16;
                int kc    = ks * 8 + c;
                a_frag[mi][0] = hs[rbase + g][kc];
                a_frag[mi][1] = hs[rbase + 8 + g][kc];
                a_frag[mi][2] = hs[rbase + g][kc + 4];
                a_frag[mi][3] = hs[rbase + 8 + g][kc + 4];
            }
#pragma unroll
            for (int ni = 0; ni < 8; ++ni) {
                int ncol = wn * 64 + ni * 8 + g;
                unsigned b0 = ws[ks * 8 + c][ncol];
                unsigned b1 = ws[ks * 8 + c + 4][ncol];
#pragma unroll
                for (int mi = 0; mi < 2; ++mi) {
                    mma_tf32(acc[mi][ni],
                             a_frag[mi][0], a_frag[mi][1], a_frag[mi][2], a_frag[mi][3],
                             b0, b1);
                }
            }
        }
    }

    // ---- epilogue: + b_join, write fp32 ----
#pragma unroll
    for (int ni = 0; ni < 8; ++ni) {
        int gcol = col0 + wn * 64 + ni * 8 + c * 2;
        float2 bb = *(const float2*)&bj[gcol];
#pragma unroll
        for (int mi = 0; mi < 2; ++mi) {
            int grow = row0 + wm * 32 + mi * 16 + g;
            float2 v0 = make_float2(acc[mi][ni][0] + bb.x, acc[mi][ni][1] + bb.y);
            float2 v1 = make_float2(acc[mi][ni][2] + bb.x, acc[mi][ni][3] + bb.y);
            *(float2*)&out[(size_t)grow * C_ + gcol]       = v0;
            *(float2*)&out[(size_t)(grow + 8) * C_ + gcol] = v1;
        }
    }
}

// ---------------------------------------------------------------------------
// launch
// ---------------------------------------------------------------------------
extern "C" void kernel_launch(void* const* d_in, const int* in_sizes, int n_in,
                              void* d_out, int out_size)
{
    const float* enc     = (const float*)d_in[0];  // [B,M,D]
    const float* dec     = (const float*)d_in[1];  // [B,N,D]
    const float* w_audio = (const float*)d_in[2];  // [D,J]
    const float* b_audio = (const float*)d_in[3];  // [J]
    const float* w_text  = (const float*)d_in[4];  // [D,J]
    const float* b_text  = (const float*)d_in[5];  // [J]
    const float* w_join  = (const float*)d_in[6];  // [J,C]
    const float* b_join  = (const float*)d_in[7];  // [C]
    float* out = (float*)d_out;

    // projections: a = enc@w_audio+b  (768 rows), t = dec@w_text+b (192 rows)
    proj_kernel<<<(B_ * M_) / 8, 320>>>(enc, w_audio, b_audio, /*which=*/0);
    proj_kernel<<<(B_ * N_) / 8, 320>>>(dec, w_text,  b_text,  /*which=*/1);

    // fused tanh-join GEMM
    dim3 grid(C_ / BN, RTOT_ / BM);   // (8, 576)
    join_kernel<<<grid, 256>>>(w_join, b_join, out);
}

// round 4
// speedup vs baseline: 1.4752x; 1.4752x over previous
#include <cuda_runtime.h>
#include <cstdint>
#include <cstddef>

// Problem dims
#define B_ 2
#define M_ 384
#define N_ 96
#define D_ 512
#define J_ 640
#define C_ 1024
#define MN_ (M_*N_)        // 36864
#define RTOT_ (B_*MN_)     // 73728

// Join tiling
#define BM 128
#define BN 256
#define BK 32
#define NKT (J_/BK)        // 20
#define THREADS 512

// padded smem row strides (floats)
#define HS_STRIDE 36       // 36 % 32 == 4 -> a-frag conflict-free
#define WS_STRIDE 264      // 264 % 32 == 8 -> b-frag conflict-free

// smem byte offsets
#define SM_AOFF  0
#define SM_TOFF  512
#define SM_HS    1024
#define HS_BYTES (BM*HS_STRIDE*4)       // 18432
#define SM_WS    (SM_HS + 2*HS_BYTES)   // 37888
#define WS_BYTES (BK*WS_STRIDE*4)       // 33792
#define SMEM_TOTAL (SM_WS + 2*WS_BYTES) // 105472

// Scratch (device globals)
__device__ float g_a[B_*M_*J_];       // audio proj + bias
__device__ float g_t[B_*N_*J_];       // text proj + bias
__device__ float g_wr[(size_t)J_*C_]; // w_join, tf32-RN-rounded (same [J,C] layout)

// ---------------------------------------------------------------------------
// helpers
// ---------------------------------------------------------------------------
__device__ __forceinline__ uint32_t smem_u32(const void* p) {
    uint32_t a;
    asm("{ .reg .u64 t; cvta.to.shared.u64 t, %1; cvt.u32.u64 %0, t; }"
        : "=r"(a) : "l"(p));
    return a;
}
__device__ __forceinline__ unsigned f2tf32(float x) {
    unsigned r;
    asm("cvt.rna.tf32.f32 %0, %1;" : "=r"(r) : "f"(x));
    return r;
}
__device__ __forceinline__ float fast_tanh(float x) {
    float r;
    asm("tanh.approx.f32 %0, %1;" : "=f"(r) : "f"(x));
    return r;
}
__device__ __forceinline__ void mma_tf32(float d[4],
                                         unsigned a0, unsigned a1, unsigned a2, unsigned a3,
                                         unsigned b0, unsigned b1) {
    asm volatile(
        "mma.sync.aligned.m16n8k8.row.col.f32.tf32.tf32.f32 "
        "{%0,%1,%2,%3}, {%4,%5,%6,%7}, {%8,%9}, {%0,%1,%2,%3};"
        : "+f"(d[0]), "+f"(d[1]), "+f"(d[2]), "+f"(d[3])
        : "r"(a0), "r"(a1), "r"(a2), "r"(a3), "r"(b0), "r"(b1));
}
__device__ __forceinline__ void cp_async16(uint32_t dst, const void* src) {
    asm volatile("cp.async.ca.shared.global [%0], [%1], 16;" :: "r"(dst), "l"(src));
}
#define CP_COMMIT() asm volatile("cp.async.commit_group;" ::: "memory")
#define CP_WAIT0()  asm volatile("cp.async.wait_group 0;" ::: "memory")

// ---------------------------------------------------------------------------
// w_join -> tf32-rounded copy
// ---------------------------------------------------------------------------
__global__ __launch_bounds__(256) void wround_kernel(const float* __restrict__ wj) {
    size_t i = (size_t)blockIdx.x * 1024 + threadIdx.x * 4;
    float4 v = *(const float4*)(wj + i);
    uint4 q;
    q.x = f2tf32(v.x); q.y = f2tf32(v.y); q.z = f2tf32(v.z); q.w = f2tf32(v.w);
    *(uint4*)((unsigned*)g_wr + i) = q;
}

// ---------------------------------------------------------------------------
// Projection: out[rows,J] = x[rows,D] @ w[D,J] + bias. 4 rows/block, J split 2.
// ---------------------------------------------------------------------------
__global__ __launch_bounds__(320) void proj_kernel(
    const float* __restrict__ x, const float* __restrict__ w,
    const float* __restrict__ bias, int which)
{
    __shared__ float xs[4][D_];
    float* outp = which ? g_t : g_a;
    const int r0 = blockIdx.x * 4;
    const int j  = blockIdx.y * 320 + threadIdx.x;

    for (int i = threadIdx.x; i < 4 * D_; i += 320)
        xs[i >> 9][i & (D_ - 1)] = x[(r0 + (i >> 9)) * D_ + (i & (D_ - 1))];
    __syncthreads();

    float a0 = 0.f, a1 = 0.f, a2 = 0.f, a3 = 0.f;
#pragma unroll 8
    for (int k = 0; k < D_; ++k) {
        float wv = w[(size_t)k * J_ + j];
        a0 += xs[0][k] * wv; a1 += xs[1][k] * wv;
        a2 += xs[2][k] * wv; a3 += xs[3][k] * wv;
    }
    float bb = bias[j];
    outp[(r0 + 0) * J_ + j] = a0 + bb;
    outp[(r0 + 1) * J_ + j] = a1 + bb;
    outp[(r0 + 2) * J_ + j] = a2 + bb;
    outp[(r0 + 3) * J_ + j] = a3 + bb;
}

// ---------------------------------------------------------------------------
// Fused join GEMM: out[gr, c] = tanh(a[gr]+t[gr]) . w[:,c] + b[c]
// 512 threads, 16 warps (4 m x 4 n), warp tile 32x64, tf32 mma.sync.
// Double-buffered: h tile via LDG+tanh+STS, w tile via cp.async.
// ---------------------------------------------------------------------------
__global__ __launch_bounds__(THREADS, 1) void join_kernel(
    const float* __restrict__ bj, float* __restrict__ out)
{
    extern __shared__ char sm[];
    const uint32_t sb = smem_u32(sm);
    const int tid  = threadIdx.x;
    const int wid  = tid >> 5;
    const int lane = tid & 31;
    const int col0 = blockIdx.x * BN;
    const int row0 = blockIdx.y * BM;

    int* aoffS = (int*)(sm + SM_AOFF);
    int* toffS = (int*)(sm + SM_TOFF);
    if (tid < BM) {
        int gr  = row0 + tid;
        int b   = gr / MN_;
        int rem = gr - b * MN_;
        int m   = rem / N_;
        int n   = rem - m * N_;
        aoffS[tid] = (b * M_ + m) * J_;
        toffS[tid] = (b * N_ + n) * J_;
    }
    __syncthreads();

    // ---- per-thread fill mapping ----
    const int hrow = tid >> 2;          // 0..127
    const int hkb  = (tid & 3) * 8;     // 0,8,16,24
    const int aoff = aoffS[hrow];
    const int toff = toffS[hrow];

    // ---- warp compute mapping ----
    const int wm = wid & 3;             // m sub-tile (32 rows)
    const int wn = wid >> 2;            // n sub-tile (64 cols)
    const int g  = lane >> 2;
    const int c  = lane & 3;

    float acc[2][8][4];
#pragma unroll
    for (int mi = 0; mi < 2; ++mi)
#pragma unroll
        for (int ni = 0; ni < 8; ++ni)
#pragma unroll
            for (int q = 0; q < 4; ++q) acc[mi][ni][q] = 0.f;

    // ================= prologue: build tile 0 into buf 0 =================
    {
        float4 av0 = *(const float4*)(g_a + aoff + hkb);
        float4 av1 = *(const float4*)(g_a + aoff + hkb + 4);
        float4 tv0 = *(const float4*)(g_t + toff + hkb);
        float4 tv1 = *(const float4*)(g_t + toff + hkb + 4);
        // w tile 0 via cp.async
        uint32_t wbase = sb + SM_WS;
#pragma unroll
        for (int p = 0; p < 4; ++p) {
            int cid  = tid + p * THREADS;      // 0..2047
            int krow = cid >> 6;
            int colf = (cid & 63) * 4;
            cp_async16(wbase + (krow * WS_STRIDE + colf) * 4,
                       g_wr + (size_t)krow * C_ + col0 + colf);
        }
        CP_COMMIT();
        uint4 q0, q1;
        q0.x = f2tf32(fast_tanh(av0.x + tv0.x));
        q0.y = f2tf32(fast_tanh(av0.y + tv0.y));
        q0.z = f2tf32(fast_tanh(av0.z + tv0.z));
        q0.w = f2tf32(fast_tanh(av0.w + tv0.w));
        q1.x = f2tf32(fast_tanh(av1.x + tv1.x));
        q1.y = f2tf32(fast_tanh(av1.y + tv1.y));
        q1.z = f2tf32(fast_tanh(av1.z + tv1.z));
        q1.w = f2tf32(fast_tanh(av1.w + tv1.w));
        unsigned* hb = (unsigned*)(sm + SM_HS) + hrow * HS_STRIDE + hkb;
        *(uint4*)(hb)     = q0;
        *(uint4*)(hb + 4) = q1;
        CP_WAIT0();
        __syncthreads();
    }

    // ================= main loop =================
    for (int kt = 0; kt < NKT; ++kt) {
        const int buf = kt & 1;
        const int nb  = buf ^ 1;
        const unsigned* hsb = (const unsigned*)(sm + SM_HS + buf * HS_BYTES);
        const unsigned* wsb = (const unsigned*)(sm + SM_WS + buf * WS_BYTES);

        // prefetch next tile (regs + cp.async)
        float4 av0, av1, tv0, tv1;
        if (kt < NKT - 1) {
            const int k0n = (kt + 1) * BK;
            av0 = *(const float4*)(g_a + aoff + k0n + hkb);
            av1 = *(const float4*)(g_a + aoff + k0n + hkb + 4);
            tv0 = *(const float4*)(g_t + toff + k0n + hkb);
            tv1 = *(const float4*)(g_t + toff + k0n + hkb + 4);
            uint32_t wbase = sb + SM_WS + nb * WS_BYTES;
#pragma unroll
            for (int p = 0; p < 4; ++p) {
                int cid  = tid + p * THREADS;
                int krow = cid >> 6;
                int colf = (cid & 63) * 4;
                cp_async16(wbase + (krow * WS_STRIDE + colf) * 4,
                           g_wr + (size_t)(k0n + krow) * C_ + col0 + colf);
            }
            CP_COMMIT();
        }

        // compute on current buffers
#pragma unroll
        for (int ks = 0; ks < BK / 8; ++ks) {
            const int kc = ks * 8 + c;
            unsigned a_frag[2][4];
#pragma unroll
            for (int mi = 0; mi < 2; ++mi) {
                int rbase = wm * 32 + mi * 16;
                a_frag[mi][0] = hsb[(rbase + g)     * HS_STRIDE + kc];
                a_frag[mi][1] = hsb[(rbase + 8 + g) * HS_STRIDE + kc];
                a_frag[mi][2] = hsb[(rbase + g)     * HS_STRIDE + kc + 4];
                a_frag[mi][3] = hsb[(rbase + 8 + g) * HS_STRIDE + kc + 4];
            }
#pragma unroll
            for (int ni = 0; ni < 8; ++ni) {
                int ncol = wn * 64 + ni * 8 + g;
                unsigned b0 = wsb[(ks * 8 + c)     * WS_STRIDE + ncol];
                unsigned b1 = wsb[(ks * 8 + c + 4) * WS_STRIDE + ncol];
#pragma unroll
                for (int mi = 0; mi < 2; ++mi)
                    mma_tf32(acc[mi][ni],
                             a_frag[mi][0], a_frag[mi][1], a_frag[mi][2], a_frag[mi][3],
                             b0, b1);
            }
        }

        // finish next-tile h build
        if (kt < NKT - 1) {
            uint4 q0, q1;
            q0.x = f2tf32(fast_tanh(av0.x + tv0.x));
            q0.y = f2tf32(fast_tanh(av0.y + tv0.y));
            q0.z = f2tf32(fast_tanh(av0.z + tv0.z));
            q0.w = f2tf32(fast_tanh(av0.w + tv0.w));
            q1.x = f2tf32(fast_tanh(av1.x + tv1.x));
            q1.y = f2tf32(fast_tanh(av1.y + tv1.y));
            q1.z = f2tf32(fast_tanh(av1.z + tv1.z));
            q1.w = f2tf32(fast_tanh(av1.w + tv1.w));
            unsigned* hb = (unsigned*)(sm + SM_HS + nb * HS_BYTES) + hrow * HS_STRIDE + hkb;
            *(uint4*)(hb)     = q0;
            *(uint4*)(hb + 4) = q1;
            CP_WAIT0();
        }
        __syncthreads();
    }

    // ================= epilogue: + b_join, fp32 stores =================
#pragma unroll
    for (int ni = 0; ni < 8; ++ni) {
        int gcol = col0 + wn * 64 + ni * 8 + c * 2;
        float2 bb = *(const float2*)(bj + gcol);
#pragma unroll
        for (int mi = 0; mi < 2; ++mi) {
            int grow = row0 + wm * 32 + mi * 16 + g;
            float2 v0 = make_float2(acc[mi][ni][0] + bb.x, acc[mi][ni][1] + bb.y);
            float2 v1 = make_float2(acc[mi][ni][2] + bb.x, acc[mi][ni][3] + bb.y);
            *(float2*)(out + (size_t)grow * C_ + gcol)       = v0;
            *(float2*)(out + (size_t)(grow + 8) * C_ + gcol) = v1;
        }
    }
}

// ---------------------------------------------------------------------------
// launch
// ---------------------------------------------------------------------------
extern "C" void kernel_launch(void* const* d_in, const int* in_sizes, int n_in,
                              void* d_out, int out_size)
{
    const float* enc     = (const float*)d_in[0];
    const float* dec     = (const float*)d_in[1];
    const float* w_audio = (const float*)d_in[2];
    const float* b_audio = (const float*)d_in[3];
    const float* w_text  = (const float*)d_in[4];
    const float* b_text  = (const float*)d_in[5];
    const float* w_join  = (const float*)d_in[6];
    const float* b_join  = (const float*)d_in[7];
    float* out = (float*)d_out;

    static int smem_set = 0;
    if (!smem_set) {
        cudaFuncSetAttribute(join_kernel, cudaFuncAttributeMaxDynamicSharedMemorySize,
                             SMEM_TOTAL);
        smem_set = 1;
    }

    wround_kernel<<<(J_ * C_) / 1024, 256>>>(w_join);
    proj_kernel<<<dim3((B_ * M_) / 4, 2), 320>>>(enc, w_audio, b_audio, 0);
    proj_kernel<<<dim3((B_ * N_) / 4, 2), 320>>>(dec, w_text, b_text, 1);

    join_kernel<<<dim3(C_ / BN, RTOT_ / BM), THREADS, SMEM_TOTAL>>>(b_join, out);
}